// round 12
// baseline (speedup 1.0000x reference)
#include <cuda_runtime.h>
#include <math.h>

#define Bn 4
#define Cn 2
#define Tn 8
#define Hn 128
#define Wn 128
#define Nn (Tn*Hn*Wn)        // 131072
#define Dn 512
#define Pn 32
#define Fn (Cn + 3*Pn)       // 98
#define Mn 65536

#define CHUNK 4096
#define NCHUNK (Nn/CHUNK)    // 32
#define NCOMPACT (NCHUNK*Bn) // 128 compact-role blocks
#define NROWS (Tn+Hn+Wn)     // 264 table rows
#define DT 128               // d-tile
#define WM 32                // consecutive m per warp
#define MT 1024              // m per block tile (32 warps x 32)
#define NSM 148
#define NDG 4                // d-groups (512/128)
#define JGN (NSM/NDG)        // 37
#define TILES (Bn*(Mn/MT))   // 256 (64 per batch; stride 37 < 64 -> every block hits every batch)
#define SMEM_TAB (NROWS*DT*4)            // 135168 B
#define SMEM_MAIN (SMEM_TAB + MT*16)     // + 16 KB record stage = 151552 B

// scratch (no cudaMalloc allowed; zero-initialized at load)
__device__ int    g_pub[Bn*NCHUNK];    // published per-chunk count+1 (0 = not ready); reset by last reader
__device__ int    g_rd[Bn*NCHUNK];     // reader tickets per publish slot
__device__ int    g_cnt[Bn];
__device__ int    g_done[Bn];          // chunks completed per batch (records visible); reset by 148th gate passer
__device__ int    g_gate[Bn];          // gate tickets per batch
__device__ int    g_tdone;             // table-producer blocks completed; reset by 148th passer
__device__ int    g_tgate;             // table gate tickets
__device__ float4 g_rec[Bn*Mn];        // {v0, v1, vi_bits, 0} for m < cnt[b]
__device__ float  g_Etab[NROWS*Dn];    // rows: [0,8)=Et, [8,136)=Eh, [136,264)=Ew

__device__ __forceinline__ void row_info(int row, int& pos, int& base) {
    if (row < Tn)         { pos = row;           base = Cn; }
    else if (row < Tn+Hn) { pos = row - Tn;      base = Cn + Pn; }
    else                  { pos = row - Tn - Hn; base = Cn + 2*Pn; }
}

__global__ void __launch_bounds__(1024, 1) k_all(
    const int* __restrict__ mask,
    const float* __restrict__ y,
    const float* __restrict__ pw,
    const float* __restrict__ pb,
    float* __restrict__ out)
{
    extern __shared__ float s[];
    float*  stab = s;                                // [NROWS][DT]
    float4* srec = (float4*)(s + NROWS*DT);          // [MT]

    int bid  = blockIdx.x;
    int tid  = threadIdx.x;
    int warp = tid >> 5;
    int lane = tid & 31;

    // ===================== phase 1: compact + tables (blocks 0..127) =====================
    if (bid < NCOMPACT) {
        int b = bid >> 5;          // batch
        int c = bid & 31;          // chunk within batch

        const int4* mk = (const int4*)(mask + (size_t)b*Nn + c*CHUNK);
        int4 v = mk[tid];          // 4 voxels per thread
        int e[4] = { v.x, v.y, v.z, v.w };
        int cnt = (e[0] != 0) + (e[1] != 0) + (e[2] != 0) + (e[3] != 0);

        int incl = cnt;
        #pragma unroll
        for (int o = 1; o < 32; o <<= 1) {
            int n = __shfl_up_sync(0xffffffffu, incl, o);
            if (lane >= o) incl += n;
        }
        __shared__ int wsum[32];
        __shared__ int wbase[32];
        __shared__ int sbase;
        if (lane == 31) wsum[warp] = incl;
        __syncthreads();

        if (warp == 0) {
            int wv = wsum[lane];
            int wincl = wv;
            #pragma unroll
            for (int o = 1; o < 32; o <<= 1) {
                int n = __shfl_up_sync(0xffffffffu, wincl, o);
                if (lane >= o) wincl += n;
            }
            wbase[lane] = wincl - wv;
            int total = __shfl_sync(0xffffffffu, wincl, 31);

            if (lane == 0 && c < NCHUNK - 1)
                atomicExch(&g_pub[b*NCHUNK + c], total + 1);

            int contrib = 0;
            if (lane < c) {
                int p;
                while ((p = atomicAdd(&g_pub[b*NCHUNK + lane], 0)) == 0) { }
                contrib = p - 1;
                int t = atomicAdd(&g_rd[b*NCHUNK + lane], 1);
                if (t == (NCHUNK - 2 - lane)) {       // last of (31-lane) readers resets slot
                    atomicExch(&g_pub[b*NCHUNK + lane], 0);
                    atomicExch(&g_rd[b*NCHUNK + lane], 0);
                }
            }
            #pragma unroll
            for (int o = 16; o > 0; o >>= 1)
                contrib += __shfl_xor_sync(0xffffffffu, contrib, o);

            if (lane == 0) {
                sbase = contrib;
                if (c == NCHUNK - 1) {
                    int tot = contrib + total;
                    g_cnt[b] = (tot < Mn) ? tot : Mn;
                }
            }
        }
        __syncthreads();

        int r = sbase + wbase[warp] + incl - cnt;
        int vbase = c*CHUNK + tid*4;
        const float* y0 = y + (size_t)b*Cn*Nn;
        float4* rec = g_rec + b*Mn;
        #pragma unroll
        for (int j = 0; j < 4; j++) {
            if (e[j] != 0) {
                if (r < Mn) {
                    int vi = vbase + j;
                    float4 rr;
                    rr.x = __ldg(y0 + vi);
                    rr.y = __ldg(y0 + Nn + vi);
                    rr.z = __int_as_float(vi);
                    rr.w = 0.0f;
                    rec[r] = rr;
                }
                r++;
            }
        }

        // ---- table rows: bid, bid+128, and (bid<8) bid+256 ----
        __shared__ float emb3[3*32];
        int nrows = (bid < NROWS - 2*NCOMPACT) ? 3 : 2;   // first 8 blocks take a 3rd row
        if (tid < 96) {
            int rr = tid >> 5;
            int p  = tid & 31;
            if (rr < nrows) {
                int row = bid + rr*NCOMPACT;
                int pos, base; row_info(row, pos, base); (void)base;
                int j = p & 15;
                float omega = exp2f(-(float)j * (13.287712379549449f / 16.0f));  // 10000^(-j/16)
                float a = (float)pos * omega;
                float sn, cs;
                sincosf(a, &sn, &cs);
                emb3[rr*32 + p] = (p < 16) ? sn : cs;
            }
        }
        __syncthreads();

        {
            int rr0 = tid >> 9;        // 0 or 1: two rows in parallel
            int d   = tid & 511;
            for (int rr = rr0; rr < nrows; rr += 2) {
                int row = bid + rr*NCOMPACT;
                int pos, base; row_info(row, pos, base); (void)pos;
                float acc = 0.0f;
                const float* wrow = pw + d*Fn + base;
                #pragma unroll
                for (int p = 0; p < 32; p++) acc += emb3[rr*32 + p] * wrow[p];
                g_Etab[row*Dn + d] = acc;
            }
        }

        __threadfence();
        __syncthreads();
        if (tid == 0) {
            atomicAdd(&g_done[b], 1);
            atomicAdd(&g_tdone, 1);
        }
    }

    // ===================== phase 2: gated main loop (all 148 blocks) =====================
    int g  = bid & (NDG - 1);
    int jg = bid >> 2;
    int d0 = g * DT;
    int dl = lane * 4;
    int d  = d0 + dl;

    // table gate
    if (tid == 0) {
        while (atomicAdd(&g_tdone, 0) < NCOMPACT) { __nanosleep(64); }
        int t = atomicAdd(&g_tgate, 1);
        if (t == NSM - 1) { atomicExch(&g_tdone, 0); atomicExch(&g_tgate, 0); }
    }
    __syncthreads();

    for (int i = tid; i < NROWS*(DT/4); i += 1024) {
        int row = i >> 5, c4 = i & 31;
        ((float4*)stab)[i] = *(const float4*)&g_Etab[row*Dn + d0 + c4*4];
    }

    float w0[4], w1[4], bs[4];
    #pragma unroll
    for (int k = 0; k < 4; k++) {
        w0[k] = pw[(d + k)*Fn + 0];
        w1[k] = pw[(d + k)*Fn + 1];
        bs[k] = pb[d + k];
    }
    __syncthreads();

    int curb = -1;
    int cnt = 0;

    for (int tile = jg; tile < TILES; tile += JGN) {
        int b  = tile >> 6;             // batch (monotonic non-decreasing)
        int m0 = (tile & 63) * MT;

        if (b != curb) {                // per-batch record gate (each block passes each gate once)
            if (tid == 0) {
                while (atomicAdd(&g_done[b], 0) < NCHUNK) { __nanosleep(64); }
                int t = atomicAdd(&g_gate[b], 1);
                if (t == NSM - 1) { atomicExch(&g_done[b], 0); atomicExch(&g_gate[b], 0); }
            }
            __syncthreads();
            curb = b;
            cnt = g_cnt[b];
        }

        // cooperative record stage: 16 KB, one LDG.128 per thread
        srec[tid] = __ldg(g_rec + b*Mn + m0 + tid);

        if (g == 0) {
            int m = m0 + tid;
            out[(size_t)Bn*Mn*Dn + b*Mn + m] = (m < cnt) ? 0.0f : 1.0f;
        }
        __syncthreads();

        float* ob = out + (size_t)b*Mn*Dn + d;
        int mw0 = m0 + warp*WM;
        const float4* wrec = srec + warp*WM;

        int thp = -1;
        float4 sth = make_float4(bs[0], bs[1], bs[2], bs[3]);

        #pragma unroll 4
        for (int mo = 0; mo < WM; mo++) {
            float4 rj = wrec[mo];           // broadcast LDS.128
            int m = mw0 + mo;
            float4 o;
            if (m < cnt) {
                int vi = __float_as_int(rj.z);
                int th = vi >> 7;                // t*128 + h
                int w  = vi & 127;
                if (th != thp) {                 // warp-uniform
                    int t = (th >> 7) & 7;
                    int h = th & 127;
                    float4 et = *(const float4*)&stab[t*DT + dl];
                    float4 eh = *(const float4*)&stab[(Tn + h)*DT + dl];
                    sth.x = bs[0] + et.x + eh.x;
                    sth.y = bs[1] + et.y + eh.y;
                    sth.z = bs[2] + et.z + eh.z;
                    sth.w = bs[3] + et.w + eh.w;
                    thp = th;
                }
                float4 ew = *(const float4*)&stab[(Tn + Hn + w)*DT + dl];
                o.x = sth.x + ew.x + rj.x*w0[0] + rj.y*w1[0];
                o.y = sth.y + ew.y + rj.x*w0[1] + rj.y*w1[1];
                o.z = sth.z + ew.z + rj.x*w0[2] + rj.y*w1[2];
                o.w = sth.w + ew.w + rj.x*w0[3] + rj.y*w1[3];
            } else {
                o = make_float4(bs[0], bs[1], bs[2], bs[3]);
            }
            __stcs((float4*)&ob[(size_t)m*Dn], o);
        }
        __syncthreads();   // seal srec before next tile's stage
    }
}

extern "C" void kernel_launch(void* const* d_in, const int* in_sizes, int n_in,
                              void* d_out, int out_size) {
    const float* y    = (const float*)d_in[0];   // y_obs  (B,C,T,H,W)
    const int*   mask = (const int*)  d_in[1];   // mask1  (B,1,T,H,W)
    const float* pw   = (const float*)d_in[2];   // proj_w (D, F)
    const float* pb   = (const float*)d_in[3];   // proj_b (D,)
    float* out = (float*)d_out;

    static bool attr_set = false;
    if (!attr_set) {
        cudaFuncSetAttribute(k_all, cudaFuncAttributeMaxDynamicSharedMemorySize, SMEM_MAIN);
        attr_set = true;
    }
    k_all<<<NSM, 1024, SMEM_MAIN>>>(mask, y, pw, pb, out);
}

// round 13
// speedup vs baseline: 1.1159x; 1.1159x over previous
#include <cuda_runtime.h>
#include <math.h>

#define Bn 4
#define Cn 2
#define Tn 8
#define Hn 128
#define Wn 128
#define Nn (Tn*Hn*Wn)        // 131072
#define Dn 512
#define Pn 32
#define Fn (Cn + 3*Pn)       // 98
#define Mn 65536

#define CHUNK 4096
#define NCHUNK (Nn/CHUNK)    // 32
#define NROWS (Tn+Hn+Wn)     // 264 table rows
#define DT 128               // d-tile
#define WM 32                // consecutive m per warp
#define MT 1024              // m per block tile (32 warps x 32)
#define NSM 148
#define NDG 4                // d-groups (512/128)
#define JGN (NSM/NDG)        // 37 blocks per d-group
#define SMEM_TAB (NROWS*DT*4)            // 135168 B
#define SMEM_MAIN (SMEM_TAB + MT*16)     // + 16 KB record stage = 151552 B

// scratch (no cudaMalloc allowed; zero-initialized at load)
__device__ int    g_pub[Bn*NCHUNK];    // published per-chunk count+1 (0 = not ready); reset by last reader
__device__ int    g_rd[Bn*NCHUNK];     // reader tickets per slot
__device__ int    g_cnt[Bn];
__device__ int    g_idx[Bn*Mn];        // compacted voxel indices (thin records)
__device__ float  g_Etab[NROWS*Dn];    // rows: [0,8)=Et, [8,136)=Eh, [136,264)=Ew

__device__ __forceinline__ void row_info(int row, int& pos, int& base) {
    if (row < Tn)         { pos = row;           base = Cn; }
    else if (row < Tn+Hn) { pos = row - Tn;      base = Cn + Pn; }
    else                  { pos = row - Tn - Hn; base = Cn + 2*Pn; }
}

// ---------------- front-end: 128 blocks, each = compact(one chunk, idx only) + 2-3 table rows ----------------
__global__ void __launch_bounds__(512) k_fused(const int* __restrict__ mask,
                                               const float* __restrict__ pw) {
    int tid = threadIdx.x;
    int lane = tid & 31;
    int warp = tid >> 5;
    int bid = blockIdx.x;
    int b = bid >> 5;          // batch
    int c = bid & 31;          // chunk within batch

    // ---- compact: 4096 voxels, 8 per thread ----
    const int4* mk = (const int4*)(mask + (size_t)b*Nn + c*CHUNK);
    int4 va = mk[tid*2];
    int4 vb = mk[tid*2 + 1];
    int e[8] = { va.x, va.y, va.z, va.w, vb.x, vb.y, vb.z, vb.w };
    int cnt = 0;
    #pragma unroll
    for (int j = 0; j < 8; j++) cnt += (e[j] != 0);

    int incl = cnt;
    #pragma unroll
    for (int o = 1; o < 32; o <<= 1) {
        int n = __shfl_up_sync(0xffffffffu, incl, o);
        if (lane >= o) incl += n;
    }
    __shared__ int wsum[16];
    __shared__ int wbase[16];
    __shared__ int sbase;
    if (lane == 31) wsum[warp] = incl;
    __syncthreads();

    if (warp == 0) {
        int wv = (lane < 16) ? wsum[lane] : 0;
        int wincl = wv;
        #pragma unroll
        for (int o = 1; o < 16; o <<= 1) {
            int n = __shfl_up_sync(0xffffffffu, wincl, o);
            if (lane >= o) wincl += n;
        }
        if (lane < 16) wbase[lane] = wincl - wv;
        int total = __shfl_sync(0xffffffffu, wincl, 15);

        // publish own count immediately (no chain); last chunk has no readers
        if (lane == 0 && c < NCHUNK - 1)
            atomicExch(&g_pub[b*NCHUNK + c], total + 1);

        // parallel poll: lane l (< c) waits for chunk l's count
        int contrib = 0;
        if (lane < c) {
            int p;
            while ((p = atomicAdd(&g_pub[b*NCHUNK + lane], 0)) == 0) { }
            contrib = p - 1;
            // reader ticket: last of (31 - l) readers resets slot for next replay
            int t = atomicAdd(&g_rd[b*NCHUNK + lane], 1);
            if (t == (NCHUNK - 2 - lane)) {
                atomicExch(&g_pub[b*NCHUNK + lane], 0);
                atomicExch(&g_rd[b*NCHUNK + lane], 0);
            }
        }
        #pragma unroll
        for (int o = 16; o > 0; o >>= 1)
            contrib += __shfl_xor_sync(0xffffffffu, contrib, o);

        if (lane == 0) {
            sbase = contrib;
            if (c == NCHUNK - 1) {
                int tot = contrib + total;
                g_cnt[b] = (tot < Mn) ? tot : Mn;
            }
        }
    }
    __syncthreads();

    int r = sbase + wbase[warp] + incl - cnt;
    int vbase = c*CHUNK + tid*8;
    int* idx = g_idx + b*Mn;
    #pragma unroll
    for (int j = 0; j < 8; j++) {
        if (e[j] != 0) {
            if (r < Mn) idx[r] = vbase + j;
            r++;
        }
    }

    // ---- table rows: block handles rows bid, bid+128, and (bid<8) bid+256 ----
    __shared__ float emb3[3*32];
    int nrows = (bid < NROWS - 256) ? 3 : 2;   // 264-256=8 blocks take a 3rd row
    if (tid < 96) {
        int rr = tid >> 5;                     // 0..2
        int p  = tid & 31;
        if (rr < nrows) {
            int row = (rr == 0) ? bid : (rr == 1) ? bid + 128 : bid + 256;
            int pos, base; row_info(row, pos, base); (void)base;
            int j = p & 15;
            float omega = exp2f(-(float)j * (13.287712379549449f / 16.0f));  // 10000^(-j/16)
            float a = (float)pos * omega;
            float sn, cs;
            sincosf(a, &sn, &cs);
            emb3[rr*32 + p] = (p < 16) ? sn : cs;
        }
    }
    __syncthreads();

    #pragma unroll
    for (int rr = 0; rr < 3; rr++) {
        if (rr >= nrows) break;
        int row = (rr == 0) ? bid : (rr == 1) ? bid + 128 : bid + 256;
        int pos, base; row_info(row, pos, base); (void)pos;
        int d = tid;                           // 512 threads == Dn
        float acc = 0.0f;
        const float* wrow = pw + d*Fn + base;
        #pragma unroll
        for (int p = 0; p < 32; p++) acc += emb3[rr*32 + p] * wrow[p];
        g_Etab[row*Dn + d] = acc;
    }
}

// ---------------- main: persistent, stage gathers y from thin idx records ----------------
__global__ void __launch_bounds__(1024, 1) k_main(
    const float* __restrict__ y,
    const float* __restrict__ pw,
    const float* __restrict__ pb,
    float* __restrict__ out)
{
    extern __shared__ float s[];
    float*  stab = s;                                // [NROWS][DT]
    float4* srec = (float4*)(s + NROWS*DT);          // [MT]

    int bid = blockIdx.x;
    int g  = bid & (NDG - 1);           // d-group
    int jg = bid >> 2;                  // 0..36
    int d0 = g * DT;
    int tid  = threadIdx.x;
    int warp = tid >> 5;
    int lane = tid & 31;
    int dl   = lane * 4;
    int d    = d0 + dl;

    // one-time unified table fill for this block's fixed d-tile
    for (int i = tid; i < NROWS*(DT/4); i += 1024) {
        int row = i >> 5, c4 = i & 31;
        ((float4*)stab)[i] = *(const float4*)&g_Etab[row*Dn + d0 + c4*4];
    }

    float w0[4], w1[4], bs[4];
    #pragma unroll
    for (int k = 0; k < 4; k++) {
        w0[k] = pw[(d + k)*Fn + 0];
        w1[k] = pw[(d + k)*Fn + 1];
        bs[k] = pb[d + k];
    }
    int cnt4[Bn];
    #pragma unroll
    for (int k = 0; k < Bn; k++) cnt4[k] = __ldg(&g_cnt[k]);
    __syncthreads();

    const int TILES = Bn * (Mn / MT);   // 256

    for (int tile = jg; tile < TILES; tile += JGN) {
        int b  = tile >> 6;
        int m0 = (tile & 63) * MT;
        int cnt = cnt4[b];
        const float* y0 = y + (size_t)b*Cn*Nn;

        // stage: idx load + near-coalesced y gather (y is L2-resident, indices ascend)
        {
            int vi = __ldg(g_idx + b*Mn + m0 + tid) & (Nn - 1);   // garbage tail stays in-range
            float v0 = __ldg(y0 + vi);
            float v1 = __ldg(y0 + Nn + vi);
            srec[tid] = make_float4(v0, v1, __int_as_float(vi), 0.0f);
        }

        if (g == 0) {
            int m = m0 + tid;
            out[(size_t)Bn*Mn*Dn + b*Mn + m] = (m < cnt) ? 0.0f : 1.0f;
        }
        __syncthreads();

        float* ob = out + (size_t)b*Mn*Dn + d;
        int mw0 = m0 + warp*WM;             // this warp's 32 consecutive m
        const float4* wrec = srec + warp*WM;

        int thp = -1;
        float4 sth = make_float4(bs[0], bs[1], bs[2], bs[3]);

        #pragma unroll 4
        for (int mo = 0; mo < WM; mo++) {
            float4 rj = wrec[mo];           // broadcast LDS.128
            int m = mw0 + mo;
            float4 o;
            if (m < cnt) {
                int vi = __float_as_int(rj.z);
                int th = vi >> 7;                // t*128 + h
                int w  = vi & 127;
                if (th != thp) {                 // warp-uniform
                    int t = (th >> 7) & 7;
                    int h = th & 127;
                    float4 et = *(const float4*)&stab[t*DT + dl];
                    float4 eh = *(const float4*)&stab[(Tn + h)*DT + dl];
                    sth.x = bs[0] + et.x + eh.x;
                    sth.y = bs[1] + et.y + eh.y;
                    sth.z = bs[2] + et.z + eh.z;
                    sth.w = bs[3] + et.w + eh.w;
                    thp = th;
                }
                float4 ew = *(const float4*)&stab[(Tn + Hn + w)*DT + dl];
                o.x = sth.x + ew.x + rj.x*w0[0] + rj.y*w1[0];
                o.y = sth.y + ew.y + rj.x*w0[1] + rj.y*w1[1];
                o.z = sth.z + ew.z + rj.x*w0[2] + rj.y*w1[2];
                o.w = sth.w + ew.w + rj.x*w0[3] + rj.y*w1[3];
            } else {
                o = make_float4(bs[0], bs[1], bs[2], bs[3]);
            }
            __stcs((float4*)&ob[(size_t)m*Dn], o);
        }
        __syncthreads();   // protect srec before next tile's stage
    }
}

extern "C" void kernel_launch(void* const* d_in, const int* in_sizes, int n_in,
                              void* d_out, int out_size) {
    const float* y    = (const float*)d_in[0];   // y_obs  (B,C,T,H,W)
    const int*   mask = (const int*)  d_in[1];   // mask1  (B,1,T,H,W)
    const float* pw   = (const float*)d_in[2];   // proj_w (D, F)
    const float* pb   = (const float*)d_in[3];   // proj_b (D,)
    float* out = (float*)d_out;

    k_fused<<<Bn*NCHUNK, 512>>>(mask, pw);       // launch 0: 128 blocks (idx + tables only)

    static bool attr_set = false;
    if (!attr_set) {
        cudaFuncSetAttribute(k_main, cudaFuncAttributeMaxDynamicSharedMemorySize, SMEM_MAIN);
        attr_set = true;
    }
    k_main<<<NSM, 1024, SMEM_MAIN>>>(y, pw, pb, out);   // launch 1
}